// round 12
// baseline (speedup 1.0000x reference)
#include <cuda_runtime.h>
#include <cuda_bf16.h>
#include <cstdint>
#include <cstddef>

// ---------------- problem dims ----------------
#define WORDN 30000
#define FDIM  80000
#define Bz 32
#define Lz 64
#define Tz 2048
#define Kz 6
#define Dz 256
#define Hz 8
#define FFDz 512
#define DFFz 1024
#define NLz 2
#define EPSz 1e-5f

__device__ __forceinline__ uint32_t smem_u32(const void* p) {
    uint32_t a;
    asm("{ .reg .u64 t; cvta.to.shared.u64 t, %1; cvt.u32.u64 %0, t; }" : "=r"(a) : "l"(p));
    return a;
}

__device__ __forceinline__ void ldsm4(uint32_t* r, uint32_t addr) {
    asm volatile("ldmatrix.sync.aligned.m8n8.x4.shared.b16 {%0,%1,%2,%3}, [%4];"
        : "=r"(r[0]), "=r"(r[1]), "=r"(r[2]), "=r"(r[3]) : "r"(addr));
}

__device__ __forceinline__ void mma16816(float* d, const uint32_t* a, const uint32_t* b) {
    asm volatile("mma.sync.aligned.m16n8k16.row.col.f32.bf16.bf16.f32 "
        "{%0,%1,%2,%3}, {%4,%5,%6,%7}, {%8,%9}, {%0,%1,%2,%3};"
        : "+f"(d[0]), "+f"(d[1]), "+f"(d[2]), "+f"(d[3])
        : "r"(a[0]), "r"(a[1]), "r"(a[2]), "r"(a[3]), "r"(b[0]), "r"(b[1]));
}

__device__ __forceinline__ void cp_async16(uint32_t saddr, const void* gptr) {
    asm volatile("cp.async.cg.shared.global [%0], [%1], 16;" :: "r"(saddr), "l"(gptr));
}
#define CP_COMMIT() asm volatile("cp.async.commit_group;" ::: "memory")
#define CP_WAIT0()  asm volatile("cp.async.wait_group 0;" ::: "memory")
#define CP_WAIT1()  asm volatile("cp.async.wait_group 1;" ::: "memory")

// ================= scratch (no allocation allowed) =================
__device__ __align__(128) __nv_bfloat16 g_wfc2h[FFDz * Dz],         g_wfc2l[FFDz * Dz];
__device__ __align__(128) __nv_bfloat16 g_wqkvh[NLz * 3 * Dz * Dz], g_wqkvl[NLz * 3 * Dz * Dz];
__device__ __align__(128) __nv_bfloat16 g_wouth[NLz * Dz * Dz],     g_woutl[NLz * Dz * Dz];
__device__ __align__(128) __nv_bfloat16 g_wff1h[NLz * DFFz * Dz],   g_wff1l[NLz * DFFz * Dz];
__device__ __align__(128) __nv_bfloat16 g_wff2h[NLz * Dz * DFFz],   g_wff2l[NLz * Dz * DFFz];
__device__ __align__(128) __nv_bfloat16 g_h0h[Tz * FFDz],  g_h0l[Tz * FFDz];
__device__ __align__(128) __nv_bfloat16 g_xh[Tz * Dz],     g_xl[Tz * Dz];
__device__ __align__(128) __nv_bfloat16 g_aoh[Tz * Dz],    g_aol[Tz * Dz];
__device__ __align__(128) __nv_bfloat16 g_f1h[Tz * DFFz],  g_f1l[Tz * DFFz];
__device__ __align__(128) float g_x[Tz * Dz];
__device__ __align__(128) float g_qkv[Tz * 3 * Dz];
__device__ __align__(128) float g_obuf[Tz * Dz];
__device__ __align__(128) float g_obuf2[Tz * Dz];  // split-K second partial (out-proj)
__device__ __align__(128) float g_f2[Tz * Dz];
__device__ __align__(128) float g_f2b[Tz * Dz];    // split-K second partial (ff2)

// ================= fused embed + weight-convert (one launch) =================
#define CE0 131072
#define CE1 524288
#define CE2 655360
#define CE3 1179648
#define CE4 1703936
#define EMB_BLKS 512
#define CVT_BLKS 832        // 832*512*4 = 1703936 = CE4

__global__ __launch_bounds__(512) void embed_convert_kernel(
    const int* __restrict__ word, const int* __restrict__ ngram,
    const float* __restrict__ fc1w, const float* __restrict__ fc1b,
    __nv_bfloat16* __restrict__ h0h, __nv_bfloat16* __restrict__ h0l,
    const float* __restrict__ fc2, const float* __restrict__ qkvw,
    const float* __restrict__ outw, const float* __restrict__ ff1,
    const float* __restrict__ ff2,
    __nv_bfloat16* __restrict__ fc2h, __nv_bfloat16* __restrict__ fc2l,
    __nv_bfloat16* __restrict__ qh,   __nv_bfloat16* __restrict__ ql,
    __nv_bfloat16* __restrict__ ohw,  __nv_bfloat16* __restrict__ olw,
    __nv_bfloat16* __restrict__ f1h,  __nv_bfloat16* __restrict__ f1l,
    __nv_bfloat16* __restrict__ f2h,  __nv_bfloat16* __restrict__ f2l)
{
    if (blockIdx.x < EMB_BLKS) {
        int t0 = blockIdx.x * 4;
        __shared__ int cols[4][7];
        __shared__ float msk[4][7];
        if (threadIdx.x < 4) {
            int tt = threadIdx.x;
            int t = t0 + tt;
            cols[tt][0] = word[t];
            msk[tt][0] = 1.f;
            #pragma unroll
            for (int k = 0; k < Kz; k++) {
                int c = WORDN + ngram[t * Kz + k];
                bool dup = false;
                for (int j = 1; j <= k; j++) if (cols[tt][j] == c) dup = true;
                cols[tt][k + 1] = c;
                msk[tt][k + 1] = dup ? 0.f : 1.f;
            }
        }
        __syncthreads();
        int r = threadIdx.x;
        const float* row = fc1w + (size_t)r * FDIM;
        float bias0 = fc1b[r];
        float acc[4] = {bias0, bias0, bias0, bias0};
        #pragma unroll
        for (int tt = 0; tt < 4; tt++)
            #pragma unroll
            for (int i = 0; i < 7; i++)
                acc[tt] += msk[tt][i] * __ldg(row + cols[tt][i]);
        #pragma unroll
        for (int tt = 0; tt < 4; tt++) {
            float s = fmaxf(acc[tt], 0.0f);
            __nv_bfloat16 h = __float2bfloat16(s);
            size_t o = (size_t)(t0 + tt) * FFDz + r;
            h0h[o] = h;
            h0l[o] = __float2bfloat16(s - __bfloat162float(h));
        }
    } else {
        long q = (long)(blockIdx.x - EMB_BLKS) * 512 + threadIdx.x;
        long i = q * 4;
        if (i >= CE4) return;
        const float* s; __nv_bfloat16 *hp, *lp; long off;
        if (i < CE0)      { s = fc2;  hp = fc2h; lp = fc2l; off = i; }
        else if (i < CE1) { s = qkvw; hp = qh;   lp = ql;   off = i - CE0; }
        else if (i < CE2) { s = outw; hp = ohw;  lp = olw;  off = i - CE1; }
        else if (i < CE3) { s = ff1;  hp = f1h;  lp = f1l;  off = i - CE2; }
        else              { s = ff2;  hp = f2h;  lp = f2l;  off = i - CE3; }
        float4 v = *(const float4*)(s + off);
        __nv_bfloat16 h0 = __float2bfloat16(v.x), h1 = __float2bfloat16(v.y);
        __nv_bfloat16 h2 = __float2bfloat16(v.z), h3 = __float2bfloat16(v.w);
        *(__nv_bfloat162*)(hp + off)     = __nv_bfloat162(h0, h1);
        *(__nv_bfloat162*)(hp + off + 2) = __nv_bfloat162(h2, h3);
        *(__nv_bfloat162*)(lp + off)     = __nv_bfloat162(
            __float2bfloat16(v.x - __bfloat162float(h0)),
            __float2bfloat16(v.y - __bfloat162float(h1)));
        *(__nv_bfloat162*)(lp + off + 2) = __nv_bfloat162(
            __float2bfloat16(v.z - __bfloat162float(h2)),
            __float2bfloat16(v.w - __bfloat162float(h3)));
    }
}

// ================= split-bf16 GEMM via mma.sync m16n8k16 (cp.async pipelined) ====
template<bool RELU, bool WF32, bool WBF16, int KSPLIT, int STAGES>
__global__ __launch_bounds__(256) void gemm_mma(
    const __nv_bfloat16* __restrict__ Ahi, const __nv_bfloat16* __restrict__ Alo,
    const __nv_bfloat16* __restrict__ Whi, const __nv_bfloat16* __restrict__ Wlo,
    const float* __restrict__ bias, float* __restrict__ C,
    __nv_bfloat16* __restrict__ Chi, __nv_bfloat16* __restrict__ Clo,
    float* __restrict__ C2, int N, int K)
{
    extern __shared__ __align__(16) char dsm[];
    constexpr uint32_t ABY  = 64 * 80u;
    constexpr uint32_t AALL = 2 * ABY;
    constexpr uint32_t BOFF = STAGES * AALL;
    constexpr uint32_t BBY  = 64 * 80u;
    constexpr uint32_t BALL = 2 * BBY;

    uint32_t sb = smem_u32(dsm);
    int tid = threadIdx.x, lane = tid & 31, wid = tid >> 5;
    int warp_m = wid & 3, warp_n = wid >> 2;
    int m0 = blockIdx.y * 64, n0 = blockIdx.x * 64;
    int kz = (KSPLIT > 1) ? blockIdx.z : 0;

    float acc[4][4];
    #pragma unroll
    for (int ni = 0; ni < 4; ni++)
        #pragma unroll
        for (int j = 0; j < 4; j++) acc[ni][j] = 0.f;

    int nkl = (K / KSPLIT) >> 5;
    int kc0 = kz * nkl;

    auto load_chunk = [&](int kc, int st) {
        size_t kb = (size_t)kc * 32;
        {
            int row = tid >> 2, ch = tid & 3;
            size_t g = (size_t)(m0 + row) * K + kb + ch * 8;
            uint32_t sa = sb + (uint32_t)st * AALL + row * 80 + ch * 16;
            cp_async16(sa,       Ahi + g);
            cp_async16(sa + ABY, Alo + g);
        }
        {
            int row = tid >> 2, ch = tid & 3;
            size_t g = (size_t)(n0 + row) * K + kb + ch * 8;
            uint32_t sa = sb + BOFF + (uint32_t)st * BALL + row * 80 + ch * 16;
            cp_async16(sa,       Whi + g);
            cp_async16(sa + BBY, Wlo + g);
        }
    };

    auto compute_chunk = [&](int st) {
        uint32_t aB = sb + (uint32_t)st * AALL;
        uint32_t bB = sb + BOFF + (uint32_t)st * BALL;
        uint32_t afA[2][2][4];
        #pragma unroll
        for (int ks = 0; ks < 2; ks++) {
            uint32_t row = warp_m * 16 + (lane & 15);
            uint32_t cb  = ks * 32 + (lane >> 4) * 16;
            uint32_t off = row * 80 + cb;
            ldsm4(afA[ks][0], aB + off);
            ldsm4(afA[ks][1], aB + ABY + off);
        }
        #pragma unroll
        for (int ks = 0; ks < 2; ks++) {
            uint32_t bf[2][2][4];
            #pragma unroll
            for (int n2 = 0; n2 < 2; n2++) {
                uint32_t nrow = warp_n * 32 + n2 * 16 + ((lane >> 4) & 1) * 8 + (lane & 7);
                uint32_t kb_  = ks * 32 + ((lane >> 3) & 1) * 16;
                uint32_t off  = nrow * 80 + kb_;
                ldsm4(bf[0][n2], bB + off);
                ldsm4(bf[1][n2], bB + BBY + off);
            }
            #pragma unroll
            for (int ni = 0; ni < 4; ni++) {
                int n2 = ni >> 1, s = (ni & 1) * 2;
                uint32_t bh[2] = {bf[0][n2][s], bf[0][n2][s + 1]};
                uint32_t bl[2] = {bf[1][n2][s], bf[1][n2][s + 1]};
                mma16816(acc[ni], afA[ks][0], bh);   // Ahi*Whi
                mma16816(acc[ni], afA[ks][1], bh);   // Alo*Whi
                mma16816(acc[ni], afA[ks][0], bl);   // Ahi*Wlo
            }
        }
    };

    if (STAGES == 3) {
        load_chunk(kc0, 0);
        CP_COMMIT();
        if (nkl > 1) { load_chunk(kc0 + 1, 1); CP_COMMIT(); CP_WAIT1(); }
        else CP_WAIT0();
        __syncthreads();
        for (int c = 0; c < nkl; c++) {
            if (c + 2 < nkl) { load_chunk(kc0 + c + 2, (c + 2) % 3); CP_COMMIT(); }
            compute_chunk(c % 3);
            if (c + 1 < nkl) {
                if (c + 2 < nkl) CP_WAIT1(); else CP_WAIT0();
                __syncthreads();
            }
        }
    } else {
        load_chunk(kc0, 0);
        CP_COMMIT();
        CP_WAIT0();
        __syncthreads();
        for (int c = 0; c < nkl; c++) {
            if (c + 1 < nkl) { load_chunk(kc0 + c + 1, (c + 1) & 1); CP_COMMIT(); }
            compute_chunk(c & 1);
            if (c + 1 < nkl) { CP_WAIT0(); __syncthreads(); }
        }
    }

    // epilogue
    float* Cw = (KSPLIT > 1 && kz > 0) ? C2 : C;
    #pragma unroll
    for (int ni = 0; ni < 4; ni++) {
        int r = m0 + warp_m * 16 + (lane >> 2);
        int cc = n0 + warp_n * 32 + ni * 8 + (lane & 3) * 2;
        float b0 = 0.f, b1 = 0.f;
        if (kz == 0) { b0 = bias[cc]; b1 = bias[cc + 1]; }
        float v00 = acc[ni][0] + b0, v01 = acc[ni][1] + b1;
        float v10 = acc[ni][2] + b0, v11 = acc[ni][3] + b1;
        if (RELU) {
            v00 = fmaxf(v00, 0.f); v01 = fmaxf(v01, 0.f);
            v10 = fmaxf(v10, 0.f); v11 = fmaxf(v11, 0.f);
        }
        size_t o0 = (size_t)r * N + cc;
        size_t o1 = (size_t)(r + 8) * N + cc;
        if (WF32) {
            *(float2*)(Cw + o0) = make_float2(v00, v01);
            *(float2*)(Cw + o1) = make_float2(v10, v11);
        }
        if (WBF16) {
            __nv_bfloat16 h00 = __float2bfloat16(v00), h01 = __float2bfloat16(v01);
            __nv_bfloat16 h10 = __float2bfloat16(v10), h11 = __float2bfloat16(v11);
            *(__nv_bfloat162*)(Chi + o0) = __nv_bfloat162(h00, h01);
            *(__nv_bfloat162*)(Chi + o1) = __nv_bfloat162(h10, h11);
            *(__nv_bfloat162*)(Clo + o0) = __nv_bfloat162(
                __float2bfloat16(v00 - __bfloat162float(h00)),
                __float2bfloat16(v01 - __bfloat162float(h01)));
            *(__nv_bfloat162*)(Clo + o1) = __nv_bfloat162(
                __float2bfloat16(v10 - __bfloat162float(h10)),
                __float2bfloat16(v11 - __bfloat162float(h11)));
        }
    }
}

// ================= attention: one block per (b, h, query-half), 256 threads ======
// Grid 512 (vs 256): 32 query rows per block, full K/V. 8 threads per query row.
__global__ __launch_bounds__(256) void attn_kernel(
    const float* __restrict__ qkv,
    __nv_bfloat16* __restrict__ oh, __nv_bfloat16* __restrict__ ol)
{
    int bh = blockIdx.x >> 1;
    int half = blockIdx.x & 1;
    int b = bh >> 3, h = bh & 7;
    int q0 = half * 32;
    __shared__ float Q[32][36], Ksm[64][36], V[64][36];
    __shared__ float S[32][68];
    int tid = threadIdx.x;
    const float scale = 0.17677669529663687f;  // 1/sqrt(32)

    // load Q half (32x32)
    for (int idx = tid; idx < 32 * 32; idx += 256) {
        int l = idx >> 5, j = idx & 31;
        Q[l][j] = qkv[(size_t)(b * 64 + q0 + l) * (3 * Dz) + h * 32 + j];
    }
    // load K, V full (64x32 each)
    for (int idx = tid; idx < 64 * 32; idx += 256) {
        int l = idx >> 5, j = idx & 31;
        size_t base = (size_t)(b * 64 + l) * (3 * Dz) + h * 32 + j;
        Ksm[l][j] = qkv[base + Dz];
        V[l][j]   = qkv[base + 2 * Dz];
    }
    __syncthreads();

    int i = tid >> 3, g = tid & 7;      // query row (0..31), lane-group (0..7)
    float4 qr[8];
    #pragma unroll
    for (int u = 0; u < 8; u++) qr[u] = *(float4*)&Q[i][u * 4];

    float sv[8];
    #pragma unroll
    for (int t = 0; t < 8; t++) {
        int j = g + t * 8;
        float s = 0.f;
        #pragma unroll
        for (int u = 0; u < 8; u++) {
            float4 kv = *(float4*)&Ksm[j][u * 4];
            s += qr[u].x * kv.x + qr[u].y * kv.y + qr[u].z * kv.z + qr[u].w * kv.w;
        }
        sv[t] = s * scale;
    }
    // softmax across the 8 lanes of this row
    float m = -1e30f;
    #pragma unroll
    for (int t = 0; t < 8; t++) m = fmaxf(m, sv[t]);
    m = fmaxf(m, __shfl_xor_sync(0xffffffffu, m, 1));
    m = fmaxf(m, __shfl_xor_sync(0xffffffffu, m, 2));
    m = fmaxf(m, __shfl_xor_sync(0xffffffffu, m, 4));
    float sum = 0.f;
    #pragma unroll
    for (int t = 0; t < 8; t++) { sv[t] = __expf(sv[t] - m); sum += sv[t]; }
    sum += __shfl_xor_sync(0xffffffffu, sum, 1);
    sum += __shfl_xor_sync(0xffffffffu, sum, 2);
    sum += __shfl_xor_sync(0xffffffffu, sum, 4);
    float inv = 1.f / sum;
    #pragma unroll
    for (int t = 0; t < 8; t++) S[i][g + t * 8] = sv[t] * inv;
    __syncthreads();

    // AV: thread handles (row i2, 4 consecutive d)
    int i2 = tid >> 3, d0 = (tid & 7) * 4;
    float o[4] = {0.f, 0.f, 0.f, 0.f};
    #pragma unroll 8
    for (int j = 0; j < 64; j++) {
        float s = S[i2][j];
        float4 v0 = *(float4*)&V[j][d0];
        o[0] += s * v0.x; o[1] += s * v0.y; o[2] += s * v0.z; o[3] += s * v0.w;
    }
    size_t ob = (size_t)(b * 64 + q0 + i2) * Dz + h * 32 + d0;
    #pragma unroll
    for (int u = 0; u < 2; u++) {
        __nv_bfloat16 ha = __float2bfloat16(o[u * 2]);
        __nv_bfloat16 hb = __float2bfloat16(o[u * 2 + 1]);
        *(__nv_bfloat162*)(oh + ob + u * 2) = __nv_bfloat162(ha, hb);
        *(__nv_bfloat162*)(ol + ob + u * 2) = __nv_bfloat162(
            __float2bfloat16(o[u * 2]     - __bfloat162float(ha)),
            __float2bfloat16(o[u * 2 + 1] - __bfloat162float(hb)));
    }
}

// ================= residual add + layernorm (+ optional 2nd residual, hi/lo) =====
__global__ __launch_bounds__(256) void add_ln_kernel(
    const float* __restrict__ xin, const float* __restrict__ res,
    const float* __restrict__ res2,
    const float* __restrict__ g, const float* __restrict__ bb,
    float* __restrict__ out,
    __nv_bfloat16* __restrict__ ohi, __nv_bfloat16* __restrict__ olo)
{
    int t = blockIdx.x;
    int d = threadIdx.x;
    size_t o = (size_t)t * Dz + d;
    float v = xin[o] + res[o];
    if (res2) v += res2[o];
    float s = v, s2 = v * v;
    #pragma unroll
    for (int off = 16; off; off >>= 1) {
        s  += __shfl_xor_sync(0xffffffffu, s,  off);
        s2 += __shfl_xor_sync(0xffffffffu, s2, off);
    }
    __shared__ float ss[8], ss2[8];
    int w = d >> 5;
    if ((d & 31) == 0) { ss[w] = s; ss2[w] = s2; }
    __syncthreads();
    float ts = 0.f, ts2 = 0.f;
    #pragma unroll
    for (int i = 0; i < 8; i++) { ts += ss[i]; ts2 += ss2[i]; }
    float mean = ts * (1.f / 256.f);
    float var  = ts2 * (1.f / 256.f) - mean * mean;
    float rstd = rsqrtf(var + EPSz);
    float r = (v - mean) * rstd * g[d] + bb[d];
    out[o] = r;
    if (ohi) {
        __nv_bfloat16 h = __float2bfloat16(r);
        ohi[o] = h;
        olo[o] = __float2bfloat16(r - __bfloat162float(h));
    }
}

// ================= launch =================
extern "C" void kernel_launch(void* const* d_in, const int* in_sizes, int n_in,
                              void* d_out, int out_size)
{
    (void)in_sizes; (void)n_in; (void)out_size;
    const int*   word   = (const int*)d_in[0];
    const int*   ngram  = (const int*)d_in[1];
    const float* fc1_w  = (const float*)d_in[2];
    const float* fc1_b  = (const float*)d_in[3];
    const float* fc2_w  = (const float*)d_in[4];
    const float* fc2_b  = (const float*)d_in[5];
    const float* qkv_w  = (const float*)d_in[6];
    const float* qkv_b  = (const float*)d_in[7];
    const float* out_w  = (const float*)d_in[8];
    const float* out_b  = (const float*)d_in[9];
    const float* ln1_g  = (const float*)d_in[10];
    const float* ln1_b  = (const float*)d_in[11];
    const float* ff1_w  = (const float*)d_in[12];
    const float* ff1_b  = (const float*)d_in[13];
    const float* ff2_w  = (const float*)d_in[14];
    const float* ff2_b  = (const float*)d_in[15];
    const float* ln2_g  = (const float*)d_in[16];
    const float* ln2_b  = (const float*)d_in[17];
    float* outp = (float*)d_out;

    __nv_bfloat16 *wfc2h, *wfc2l, *wqkvh, *wqkvl, *wouth, *woutl, *wff1h, *wff1l, *wff2h, *wff2l;
    __nv_bfloat16 *h0h, *h0l, *xh, *xl, *aoh, *aol, *f1h, *f1l;
    float *x, *qkvf, *obuf, *obuf2, *f2, *f2b;
    cudaGetSymbolAddress((void**)&wfc2h, g_wfc2h); cudaGetSymbolAddress((void**)&wfc2l, g_wfc2l);
    cudaGetSymbolAddress((void**)&wqkvh, g_wqkvh); cudaGetSymbolAddress((void**)&wqkvl, g_wqkvl);
    cudaGetSymbolAddress((void**)&wouth, g_wouth); cudaGetSymbolAddress((void**)&woutl, g_woutl);
    cudaGetSymbolAddress((void**)&wff1h, g_wff1h); cudaGetSymbolAddress((void**)&wff1l, g_wff1l);
    cudaGetSymbolAddress((void**)&wff2h, g_wff2h); cudaGetSymbolAddress((void**)&wff2l, g_wff2l);
    cudaGetSymbolAddress((void**)&h0h, g_h0h);     cudaGetSymbolAddress((void**)&h0l, g_h0l);
    cudaGetSymbolAddress((void**)&xh, g_xh);       cudaGetSymbolAddress((void**)&xl, g_xl);
    cudaGetSymbolAddress((void**)&aoh, g_aoh);     cudaGetSymbolAddress((void**)&aol, g_aol);
    cudaGetSymbolAddress((void**)&f1h, g_f1h);     cudaGetSymbolAddress((void**)&f1l, g_f1l);
    cudaGetSymbolAddress((void**)&x, g_x);
    cudaGetSymbolAddress((void**)&qkvf, g_qkv);
    cudaGetSymbolAddress((void**)&obuf, g_obuf);
    cudaGetSymbolAddress((void**)&obuf2, g_obuf2);
    cudaGetSymbolAddress((void**)&f2, g_f2);
    cudaGetSymbolAddress((void**)&f2b, g_f2b);

    constexpr int SMEM2ST = 40960, SMEM3ST = 61440;
    cudaFuncSetAttribute(gemm_mma<false, true,  true,  1, 3>, cudaFuncAttributeMaxDynamicSharedMemorySize, SMEM3ST);
    cudaFuncSetAttribute(gemm_mma<false, true,  false, 1, 3>, cudaFuncAttributeMaxDynamicSharedMemorySize, SMEM3ST);
    cudaFuncSetAttribute(gemm_mma<false, true,  false, 2, 3>, cudaFuncAttributeMaxDynamicSharedMemorySize, SMEM3ST);
    cudaFuncSetAttribute(gemm_mma<true,  false, true,  1, 2>, cudaFuncAttributeMaxDynamicSharedMemorySize, SMEM2ST);

    // fused embed (4 tok/block) + weight hi/lo convert — one launch
    embed_convert_kernel<<<EMB_BLKS + CVT_BLKS, 512>>>(
        word, ngram, fc1_w, fc1_b, h0h, h0l,
        fc2_w, qkv_w, out_w, ff1_w, ff2_w,
        wfc2h, wfc2l, wqkvh, wqkvl, wouth, woutl, wff1h, wff1l, wff2h, wff2l);

    // fc2: x = h0 @ fc2_w^T + b  [2048, 256]  (fp32 + hi/lo out) — grid 4x32, 3-stage
    gemm_mma<false, true, true, 1, 3><<<dim3(Dz / 64, Tz / 64), 256, SMEM3ST>>>(
        h0h, h0l, wfc2h, wfc2l, fc2_b, x, xh, xl, nullptr, Dz, FFDz);

    for (int i = 0; i < NLz; i++) {
        const __nv_bfloat16* qwh = wqkvh + (size_t)i * 3 * Dz * Dz;
        const __nv_bfloat16* qwl = wqkvl + (size_t)i * 3 * Dz * Dz;
        const __nv_bfloat16* owh = wouth + (size_t)i * Dz * Dz;
        const __nv_bfloat16* owl = woutl + (size_t)i * Dz * Dz;
        const __nv_bfloat16* f1wh = wff1h + (size_t)i * DFFz * Dz;
        const __nv_bfloat16* f1wl = wff1l + (size_t)i * DFFz * Dz;
        const __nv_bfloat16* f2wh = wff2h + (size_t)i * Dz * DFFz;
        const __nv_bfloat16* f2wl = wff2l + (size_t)i * Dz * DFFz;

        // qkv projection [2048, 768] — grid 12x32 (384 CTAs), 3-stage
        gemm_mma<false, true, false, 1, 3><<<dim3(3 * Dz / 64, Tz / 64), 256, SMEM3ST>>>(
            xh, xl, qwh, qwl, qkv_b + (size_t)i * 3 * Dz, qkvf, nullptr, nullptr, nullptr, 3 * Dz, Dz);
        // attention — grid 512 (query-split), 256 threads
        attn_kernel<<<Bz * Hz * 2, 256>>>(qkvf, aoh, aol);
        // out projection [2048, 256], K=256 split-K=2 — grid 4x32x2 (256 CTAs), 3-stage
        gemm_mma<false, true, false, 2, 3><<<dim3(Dz / 64, Tz / 64, 2), 256, SMEM3ST>>>(
            aoh, aol, owh, owl, out_b + (size_t)i * Dz, obuf, nullptr, nullptr, obuf2, Dz, Dz);
        // x = LN(x + obuf + obuf2), fp32 + hi/lo
        add_ln_kernel<<<Tz, 256>>>(x, obuf, obuf2, ln1_g + i * Dz, ln1_b + i * Dz, x, xh, xl);
        // ff1 + relu [2048, 1024] hi/lo only — grid 16x32 (512 CTAs), 2-stage
        gemm_mma<true, false, true, 1, 2><<<dim3(DFFz / 64, Tz / 64), 256, SMEM2ST>>>(
            xh, xl, f1wh, f1wl, ff1_b + (size_t)i * DFFz, nullptr, f1h, f1l, nullptr, DFFz, Dz);
        // ff2 [2048, 256], K=1024 split-K=2 — grid 4x32x2 (256 CTAs), 3-stage
        gemm_mma<false, true, false, 2, 3><<<dim3(Dz / 64, Tz / 64, 2), 256, SMEM3ST>>>(
            f1h, f1l, f2wh, f2wl, ff2_b + (size_t)i * Dz, f2, nullptr, nullptr, f2b, Dz, DFFz);
        // x = LN(x + f2 + f2b); final layer -> d_out (fp32 only)
        bool last = (i == NLz - 1);
        add_ln_kernel<<<Tz, 256>>>(x, f2, f2b, ln2_g + i * Dz, ln2_b + i * Dz,
                                   last ? outp : x,
                                   last ? nullptr : xh, last ? nullptr : xl);
    }
}

// round 14
// speedup vs baseline: 1.0321x; 1.0321x over previous
#include <cuda_runtime.h>
#include <cuda_bf16.h>
#include <cstdint>
#include <cstddef>

// ---------------- problem dims ----------------
#define WORDN 30000
#define FDIM  80000
#define Bz 32
#define Lz 64
#define Tz 2048
#define Kz 6
#define Dz 256
#define Hz 8
#define FFDz 512
#define DFFz 1024
#define NLz 2
#define EPSz 1e-5f

__device__ __forceinline__ uint32_t smem_u32(const void* p) {
    uint32_t a;
    asm("{ .reg .u64 t; cvta.to.shared.u64 t, %1; cvt.u32.u64 %0, t; }" : "=r"(a) : "l"(p));
    return a;
}

__device__ __forceinline__ void ldsm4(uint32_t* r, uint32_t addr) {
    asm volatile("ldmatrix.sync.aligned.m8n8.x4.shared.b16 {%0,%1,%2,%3}, [%4];"
        : "=r"(r[0]), "=r"(r[1]), "=r"(r[2]), "=r"(r[3]) : "r"(addr));
}

__device__ __forceinline__ void mma16816(float* d, const uint32_t* a, const uint32_t* b) {
    asm volatile("mma.sync.aligned.m16n8k16.row.col.f32.bf16.bf16.f32 "
        "{%0,%1,%2,%3}, {%4,%5,%6,%7}, {%8,%9}, {%0,%1,%2,%3};"
        : "+f"(d[0]), "+f"(d[1]), "+f"(d[2]), "+f"(d[3])
        : "r"(a[0]), "r"(a[1]), "r"(a[2]), "r"(a[3]), "r"(b[0]), "r"(b[1]));
}

__device__ __forceinline__ void cp_async16(uint32_t saddr, const void* gptr) {
    asm volatile("cp.async.cg.shared.global [%0], [%1], 16;" :: "r"(saddr), "l"(gptr));
}
#define CP_COMMIT() asm volatile("cp.async.commit_group;" ::: "memory")
#define CP_WAIT0()  asm volatile("cp.async.wait_group 0;" ::: "memory")
#define CP_WAIT1()  asm volatile("cp.async.wait_group 1;" ::: "memory")

// ================= scratch (no allocation allowed) =================
__device__ __align__(128) __nv_bfloat16 g_wfc2h[FFDz * Dz],         g_wfc2l[FFDz * Dz];
__device__ __align__(128) __nv_bfloat16 g_wqkvh[NLz * 3 * Dz * Dz], g_wqkvl[NLz * 3 * Dz * Dz];
__device__ __align__(128) __nv_bfloat16 g_wouth[NLz * Dz * Dz],     g_woutl[NLz * Dz * Dz];
__device__ __align__(128) __nv_bfloat16 g_wff1h[NLz * DFFz * Dz],   g_wff1l[NLz * DFFz * Dz];
__device__ __align__(128) __nv_bfloat16 g_wff2h[NLz * Dz * DFFz],   g_wff2l[NLz * Dz * DFFz];
__device__ __align__(128) __nv_bfloat16 g_h0h[Tz * FFDz],  g_h0l[Tz * FFDz];
__device__ __align__(128) __nv_bfloat16 g_xh[Tz * Dz],     g_xl[Tz * Dz];
__device__ __align__(128) __nv_bfloat16 g_aoh[Tz * Dz],    g_aol[Tz * Dz];
__device__ __align__(128) __nv_bfloat16 g_f1h[Tz * DFFz],  g_f1l[Tz * DFFz];
__device__ __align__(128) float g_x[Tz * Dz];
__device__ __align__(128) float g_qkv[Tz * 3 * Dz];
__device__ __align__(128) float g_obuf[Tz * Dz];
__device__ __align__(128) float g_obuf2[Tz * Dz];  // split-K second partial (out-proj)
__device__ __align__(128) float g_f2[Tz * Dz];
__device__ __align__(128) float g_f2b[Tz * Dz];    // split-K second partial (ff2)

// ================= fused embed + weight-convert (one launch) =================
#define CE0 131072
#define CE1 524288
#define CE2 655360
#define CE3 1179648
#define CE4 1703936
#define EMB_BLKS 512
#define CVT_BLKS 832        // 832*512*4 = 1703936 = CE4

__global__ __launch_bounds__(512) void embed_convert_kernel(
    const int* __restrict__ word, const int* __restrict__ ngram,
    const float* __restrict__ fc1w, const float* __restrict__ fc1b,
    __nv_bfloat16* __restrict__ h0h, __nv_bfloat16* __restrict__ h0l,
    const float* __restrict__ fc2, const float* __restrict__ qkvw,
    const float* __restrict__ outw, const float* __restrict__ ff1,
    const float* __restrict__ ff2,
    __nv_bfloat16* __restrict__ fc2h, __nv_bfloat16* __restrict__ fc2l,
    __nv_bfloat16* __restrict__ qh,   __nv_bfloat16* __restrict__ ql,
    __nv_bfloat16* __restrict__ ohw,  __nv_bfloat16* __restrict__ olw,
    __nv_bfloat16* __restrict__ f1h,  __nv_bfloat16* __restrict__ f1l,
    __nv_bfloat16* __restrict__ f2h,  __nv_bfloat16* __restrict__ f2l)
{
    if (blockIdx.x < EMB_BLKS) {
        int t0 = blockIdx.x * 4;
        __shared__ int cols[4][7];
        __shared__ float msk[4][7];
        if (threadIdx.x < 4) {
            int tt = threadIdx.x;
            int t = t0 + tt;
            cols[tt][0] = word[t];
            msk[tt][0] = 1.f;
            #pragma unroll
            for (int k = 0; k < Kz; k++) {
                int c = WORDN + ngram[t * Kz + k];
                bool dup = false;
                for (int j = 1; j <= k; j++) if (cols[tt][j] == c) dup = true;
                cols[tt][k + 1] = c;
                msk[tt][k + 1] = dup ? 0.f : 1.f;
            }
        }
        __syncthreads();
        int r = threadIdx.x;
        const float* row = fc1w + (size_t)r * FDIM;
        float bias0 = fc1b[r];
        float acc[4] = {bias0, bias0, bias0, bias0};
        #pragma unroll
        for (int tt = 0; tt < 4; tt++)
            #pragma unroll
            for (int i = 0; i < 7; i++)
                acc[tt] += msk[tt][i] * __ldg(row + cols[tt][i]);
        #pragma unroll
        for (int tt = 0; tt < 4; tt++) {
            float s = fmaxf(acc[tt], 0.0f);
            __nv_bfloat16 h = __float2bfloat16(s);
            size_t o = (size_t)(t0 + tt) * FFDz + r;
            h0h[o] = h;
            h0l[o] = __float2bfloat16(s - __bfloat162float(h));
        }
    } else {
        long q = (long)(blockIdx.x - EMB_BLKS) * 512 + threadIdx.x;
        long i = q * 4;
        if (i >= CE4) return;
        const float* s; __nv_bfloat16 *hp, *lp; long off;
        if (i < CE0)      { s = fc2;  hp = fc2h; lp = fc2l; off = i; }
        else if (i < CE1) { s = qkvw; hp = qh;   lp = ql;   off = i - CE0; }
        else if (i < CE2) { s = outw; hp = ohw;  lp = olw;  off = i - CE1; }
        else if (i < CE3) { s = ff1;  hp = f1h;  lp = f1l;  off = i - CE2; }
        else              { s = ff2;  hp = f2h;  lp = f2l;  off = i - CE3; }
        float4 v = *(const float4*)(s + off);
        __nv_bfloat16 h0 = __float2bfloat16(v.x), h1 = __float2bfloat16(v.y);
        __nv_bfloat16 h2 = __float2bfloat16(v.z), h3 = __float2bfloat16(v.w);
        *(__nv_bfloat162*)(hp + off)     = __nv_bfloat162(h0, h1);
        *(__nv_bfloat162*)(hp + off + 2) = __nv_bfloat162(h2, h3);
        *(__nv_bfloat162*)(lp + off)     = __nv_bfloat162(
            __float2bfloat16(v.x - __bfloat162float(h0)),
            __float2bfloat16(v.y - __bfloat162float(h1)));
        *(__nv_bfloat162*)(lp + off + 2) = __nv_bfloat162(
            __float2bfloat16(v.z - __bfloat162float(h2)),
            __float2bfloat16(v.w - __bfloat162float(h3)));
    }
}

// ================= split-bf16 GEMM via mma.sync m16n8k16 (cp.async pipelined) ====
template<bool RELU, bool WF32, bool WBF16, int KSPLIT, int STAGES>
__global__ __launch_bounds__(256) void gemm_mma(
    const __nv_bfloat16* __restrict__ Ahi, const __nv_bfloat16* __restrict__ Alo,
    const __nv_bfloat16* __restrict__ Whi, const __nv_bfloat16* __restrict__ Wlo,
    const float* __restrict__ bias, float* __restrict__ C,
    __nv_bfloat16* __restrict__ Chi, __nv_bfloat16* __restrict__ Clo,
    float* __restrict__ C2, int N, int K)
{
    extern __shared__ __align__(16) char dsm[];
    constexpr uint32_t ABY  = 64 * 80u;
    constexpr uint32_t AALL = 2 * ABY;
    constexpr uint32_t BOFF = STAGES * AALL;
    constexpr uint32_t BBY  = 64 * 80u;
    constexpr uint32_t BALL = 2 * BBY;

    uint32_t sb = smem_u32(dsm);
    int tid = threadIdx.x, lane = tid & 31, wid = tid >> 5;
    int warp_m = wid & 3, warp_n = wid >> 2;
    int m0 = blockIdx.y * 64, n0 = blockIdx.x * 64;
    int kz = (KSPLIT > 1) ? blockIdx.z : 0;

    float acc[4][4];
    #pragma unroll
    for (int ni = 0; ni < 4; ni++)
        #pragma unroll
        for (int j = 0; j < 4; j++) acc[ni][j] = 0.f;

    int nkl = (K / KSPLIT) >> 5;
    int kc0 = kz * nkl;

    auto load_chunk = [&](int kc, int st) {
        size_t kb = (size_t)kc * 32;
        {
            int row = tid >> 2, ch = tid & 3;
            size_t g = (size_t)(m0 + row) * K + kb + ch * 8;
            uint32_t sa = sb + (uint32_t)st * AALL + row * 80 + ch * 16;
            cp_async16(sa,       Ahi + g);
            cp_async16(sa + ABY, Alo + g);
        }
        {
            int row = tid >> 2, ch = tid & 3;
            size_t g = (size_t)(n0 + row) * K + kb + ch * 8;
            uint32_t sa = sb + BOFF + (uint32_t)st * BALL + row * 80 + ch * 16;
            cp_async16(sa,       Whi + g);
            cp_async16(sa + BBY, Wlo + g);
        }
    };

    auto compute_chunk = [&](int st) {
        uint32_t aB = sb + (uint32_t)st * AALL;
        uint32_t bB = sb + BOFF + (uint32_t)st * BALL;
        uint32_t afA[2][2][4];
        #pragma unroll
        for (int ks = 0; ks < 2; ks++) {
            uint32_t row = warp_m * 16 + (lane & 15);
            uint32_t cb  = ks * 32 + (lane >> 4) * 16;
            uint32_t off = row * 80 + cb;
            ldsm4(afA[ks][0], aB + off);
            ldsm4(afA[ks][1], aB + ABY + off);
        }
        #pragma unroll
        for (int ks = 0; ks < 2; ks++) {
            uint32_t bf[2][2][4];
            #pragma unroll
            for (int n2 = 0; n2 < 2; n2++) {
                uint32_t nrow = warp_n * 32 + n2 * 16 + ((lane >> 4) & 1) * 8 + (lane & 7);
                uint32_t kb_  = ks * 32 + ((lane >> 3) & 1) * 16;
                uint32_t off  = nrow * 80 + kb_;
                ldsm4(bf[0][n2], bB + off);
                ldsm4(bf[1][n2], bB + BBY + off);
            }
            #pragma unroll
            for (int ni = 0; ni < 4; ni++) {
                int n2 = ni >> 1, s = (ni & 1) * 2;
                uint32_t bh[2] = {bf[0][n2][s], bf[0][n2][s + 1]};
                uint32_t bl[2] = {bf[1][n2][s], bf[1][n2][s + 1]};
                mma16816(acc[ni], afA[ks][0], bh);   // Ahi*Whi
                mma16816(acc[ni], afA[ks][1], bh);   // Alo*Whi
                mma16816(acc[ni], afA[ks][0], bl);   // Ahi*Wlo
            }
        }
    };

    if (STAGES == 3) {
        load_chunk(kc0, 0);
        CP_COMMIT();
        if (nkl > 1) { load_chunk(kc0 + 1, 1); CP_COMMIT(); CP_WAIT1(); }
        else CP_WAIT0();
        __syncthreads();
        for (int c = 0; c < nkl; c++) {
            if (c + 2 < nkl) { load_chunk(kc0 + c + 2, (c + 2) % 3); CP_COMMIT(); }
            compute_chunk(c % 3);
            if (c + 1 < nkl) {
                if (c + 2 < nkl) CP_WAIT1(); else CP_WAIT0();
                __syncthreads();
            }
        }
    } else {
        load_chunk(kc0, 0);
        CP_COMMIT();
        CP_WAIT0();
        __syncthreads();
        for (int c = 0; c < nkl; c++) {
            if (c + 1 < nkl) { load_chunk(kc0 + c + 1, (c + 1) & 1); CP_COMMIT(); }
            compute_chunk(c & 1);
            if (c + 1 < nkl) { CP_WAIT0(); __syncthreads(); }
        }
    }

    // epilogue
    float* Cw = (KSPLIT > 1 && kz > 0) ? C2 : C;
    #pragma unroll
    for (int ni = 0; ni < 4; ni++) {
        int r = m0 + warp_m * 16 + (lane >> 2);
        int cc = n0 + warp_n * 32 + ni * 8 + (lane & 3) * 2;
        float b0 = 0.f, b1 = 0.f;
        if (kz == 0) { b0 = bias[cc]; b1 = bias[cc + 1]; }
        float v00 = acc[ni][0] + b0, v01 = acc[ni][1] + b1;
        float v10 = acc[ni][2] + b0, v11 = acc[ni][3] + b1;
        if (RELU) {
            v00 = fmaxf(v00, 0.f); v01 = fmaxf(v01, 0.f);
            v10 = fmaxf(v10, 0.f); v11 = fmaxf(v11, 0.f);
        }
        size_t o0 = (size_t)r * N + cc;
        size_t o1 = (size_t)(r + 8) * N + cc;
        if (WF32) {
            *(float2*)(Cw + o0) = make_float2(v00, v01);
            *(float2*)(Cw + o1) = make_float2(v10, v11);
        }
        if (WBF16) {
            __nv_bfloat16 h00 = __float2bfloat16(v00), h01 = __float2bfloat16(v01);
            __nv_bfloat16 h10 = __float2bfloat16(v10), h11 = __float2bfloat16(v11);
            *(__nv_bfloat162*)(Chi + o0) = __nv_bfloat162(h00, h01);
            *(__nv_bfloat162*)(Chi + o1) = __nv_bfloat162(h10, h11);
            *(__nv_bfloat162*)(Clo + o0) = __nv_bfloat162(
                __float2bfloat16(v00 - __bfloat162float(h00)),
                __float2bfloat16(v01 - __bfloat162float(h01)));
            *(__nv_bfloat162*)(Clo + o1) = __nv_bfloat162(
                __float2bfloat16(v10 - __bfloat162float(h10)),
                __float2bfloat16(v11 - __bfloat162float(h11)));
        }
    }
}

// ================= attention: one block per (b,h), 256 threads ==================
// 2 query rows per thread (iq, iq+32): each K/V float4 load feeds both rows,
// halving shared-memory traffic vs 1-row-per-thread. S padded to 72 floats
// (stride ≡ 8 mod 32 -> conflict-free writes across the 4 iq-groups per warp).
__global__ __launch_bounds__(256) void attn_kernel(
    const float* __restrict__ qkv,
    __nv_bfloat16* __restrict__ oh, __nv_bfloat16* __restrict__ ol)
{
    int bh = blockIdx.x;
    int b = bh >> 3, h = bh & 7;
    __shared__ float Q[64][36], Ksm[64][36], V[64][36];
    __shared__ float S[64][72];
    int tid = threadIdx.x;
    const float scale = 0.17677669529663687f;  // 1/sqrt(32)

    for (int idx = tid; idx < 64 * 32; idx += 256) {
        int l = idx >> 5, j = idx & 31;
        size_t base = (size_t)(b * 64 + l) * (3 * Dz) + h * 32 + j;
        Q[l][j]   = qkv[base];
        Ksm[l][j] = qkv[base + Dz];
        V[l][j]   = qkv[base + 2 * Dz];
    }
    __syncthreads();

    int iq = tid >> 3, g = tid & 7;     // query row pair (iq, iq+32), lane-group
    float4 qa[8], qb[8];
    #pragma unroll
    for (int u = 0; u < 8; u++) {
        qa[u] = *(float4*)&Q[iq][u * 4];
        qb[u] = *(float4*)&Q[iq + 32][u * 4];
    }

    float sva[8], svb[8];
    #pragma unroll
    for (int t = 0; t < 8; t++) {
        int j = g + t * 8;
        float sa = 0.f, sb2 = 0.f;
        #pragma unroll
        for (int u = 0; u < 8; u++) {
            float4 kv = *(float4*)&Ksm[j][u * 4];
            sa  += qa[u].x * kv.x + qa[u].y * kv.y + qa[u].z * kv.z + qa[u].w * kv.w;
            sb2 += qb[u].x * kv.x + qb[u].y * kv.y + qb[u].z * kv.z + qb[u].w * kv.w;
        }
        sva[t] = sa * scale;
        svb[t] = sb2 * scale;
    }
    // softmax across the 8 lanes of each row (rows independent)
    float ma = -1e30f, mb = -1e30f;
    #pragma unroll
    for (int t = 0; t < 8; t++) { ma = fmaxf(ma, sva[t]); mb = fmaxf(mb, svb[t]); }
    #pragma unroll
    for (int o = 1; o <= 4; o <<= 1) {
        ma = fmaxf(ma, __shfl_xor_sync(0xffffffffu, ma, o));
        mb = fmaxf(mb, __shfl_xor_sync(0xffffffffu, mb, o));
    }
    float suma = 0.f, sumb = 0.f;
    #pragma unroll
    for (int t = 0; t < 8; t++) {
        sva[t] = __expf(sva[t] - ma); suma += sva[t];
        svb[t] = __expf(svb[t] - mb); sumb += svb[t];
    }
    #pragma unroll
    for (int o = 1; o <= 4; o <<= 1) {
        suma += __shfl_xor_sync(0xffffffffu, suma, o);
        sumb += __shfl_xor_sync(0xffffffffu, sumb, o);
    }
    float inva = 1.f / suma, invb = 1.f / sumb;
    #pragma unroll
    for (int t = 0; t < 8; t++) {
        S[iq][g + t * 8]      = sva[t] * inva;
        S[iq + 32][g + t * 8] = svb[t] * invb;
    }
    __syncthreads();

    // AV: thread = (row pair iq2/iq2+32, 4 consecutive d); V float4 reused by both rows
    int iq2 = tid >> 3, d0 = (tid & 7) * 4;
    float oa[4] = {0.f, 0.f, 0.f, 0.f};
    float ob2[4] = {0.f, 0.f, 0.f, 0.f};
    #pragma unroll 8
    for (int j = 0; j < 64; j++) {
        float sa = S[iq2][j];
        float sb2 = S[iq2 + 32][j];
        float4 v0 = *(float4*)&V[j][d0];
        oa[0] += sa * v0.x; oa[1] += sa * v0.y; oa[2] += sa * v0.z; oa[3] += sa * v0.w;
        ob2[0] += sb2 * v0.x; ob2[1] += sb2 * v0.y; ob2[2] += sb2 * v0.z; ob2[3] += sb2 * v0.w;
    }
    #pragma unroll
    for (int rr = 0; rr < 2; rr++) {
        float* o = rr ? ob2 : oa;
        int row = b * 64 + iq2 + rr * 32;
        size_t ob = (size_t)row * Dz + h * 32 + d0;
        #pragma unroll
        for (int u = 0; u < 2; u++) {
            __nv_bfloat16 ha = __float2bfloat16(o[u * 2]);
            __nv_bfloat16 hb = __float2bfloat16(o[u * 2 + 1]);
            *(__nv_bfloat162*)(oh + ob + u * 2) = __nv_bfloat162(ha, hb);
            *(__nv_bfloat162*)(ol + ob + u * 2) = __nv_bfloat162(
                __float2bfloat16(o[u * 2]     - __bfloat162float(ha)),
                __float2bfloat16(o[u * 2 + 1] - __bfloat162float(hb)));
        }
    }
}

// ================= residual add + layernorm (+ optional 2nd residual, hi/lo) =====
__global__ __launch_bounds__(256) void add_ln_kernel(
    const float* __restrict__ xin, const float* __restrict__ res,
    const float* __restrict__ res2,
    const float* __restrict__ g, const float* __restrict__ bb,
    float* __restrict__ out,
    __nv_bfloat16* __restrict__ ohi, __nv_bfloat16* __restrict__ olo)
{
    int t = blockIdx.x;
    int d = threadIdx.x;
    size_t o = (size_t)t * Dz + d;
    float v = xin[o] + res[o];
    if (res2) v += res2[o];
    float s = v, s2 = v * v;
    #pragma unroll
    for (int off = 16; off; off >>= 1) {
        s  += __shfl_xor_sync(0xffffffffu, s,  off);
        s2 += __shfl_xor_sync(0xffffffffu, s2, off);
    }
    __shared__ float ss[8], ss2[8];
    int w = d >> 5;
    if ((d & 31) == 0) { ss[w] = s; ss2[w] = s2; }
    __syncthreads();
    float ts = 0.f, ts2 = 0.f;
    #pragma unroll
    for (int i = 0; i < 8; i++) { ts += ss[i]; ts2 += ss2[i]; }
    float mean = ts * (1.f / 256.f);
    float var  = ts2 * (1.f / 256.f) - mean * mean;
    float rstd = rsqrtf(var + EPSz);
    float r = (v - mean) * rstd * g[d] + bb[d];
    out[o] = r;
    if (ohi) {
        __nv_bfloat16 h = __float2bfloat16(r);
        ohi[o] = h;
        olo[o] = __float2bfloat16(r - __bfloat162float(h));
    }
}

// ================= launch =================
extern "C" void kernel_launch(void* const* d_in, const int* in_sizes, int n_in,
                              void* d_out, int out_size)
{
    (void)in_sizes; (void)n_in; (void)out_size;
    const int*   word   = (const int*)d_in[0];
    const int*   ngram  = (const int*)d_in[1];
    const float* fc1_w  = (const float*)d_in[2];
    const float* fc1_b  = (const float*)d_in[3];
    const float* fc2_w  = (const float*)d_in[4];
    const float* fc2_b  = (const float*)d_in[5];
    const float* qkv_w  = (const float*)d_in[6];
    const float* qkv_b  = (const float*)d_in[7];
    const float* out_w  = (const float*)d_in[8];
    const float* out_b  = (const float*)d_in[9];
    const float* ln1_g  = (const float*)d_in[10];
    const float* ln1_b  = (const float*)d_in[11];
    const float* ff1_w  = (const float*)d_in[12];
    const float* ff1_b  = (const float*)d_in[13];
    const float* ff2_w  = (const float*)d_in[14];
    const float* ff2_b  = (const float*)d_in[15];
    const float* ln2_g  = (const float*)d_in[16];
    const float* ln2_b  = (const float*)d_in[17];
    float* outp = (float*)d_out;

    __nv_bfloat16 *wfc2h, *wfc2l, *wqkvh, *wqkvl, *wouth, *woutl, *wff1h, *wff1l, *wff2h, *wff2l;
    __nv_bfloat16 *h0h, *h0l, *xh, *xl, *aoh, *aol, *f1h, *f1l;
    float *x, *qkvf, *obuf, *obuf2, *f2, *f2b;
    cudaGetSymbolAddress((void**)&wfc2h, g_wfc2h); cudaGetSymbolAddress((void**)&wfc2l, g_wfc2l);
    cudaGetSymbolAddress((void**)&wqkvh, g_wqkvh); cudaGetSymbolAddress((void**)&wqkvl, g_wqkvl);
    cudaGetSymbolAddress((void**)&wouth, g_wouth); cudaGetSymbolAddress((void**)&woutl, g_woutl);
    cudaGetSymbolAddress((void**)&wff1h, g_wff1h); cudaGetSymbolAddress((void**)&wff1l, g_wff1l);
    cudaGetSymbolAddress((void**)&wff2h, g_wff2h); cudaGetSymbolAddress((void**)&wff2l, g_wff2l);
    cudaGetSymbolAddress((void**)&h0h, g_h0h);     cudaGetSymbolAddress((void**)&h0l, g_h0l);
    cudaGetSymbolAddress((void**)&xh, g_xh);       cudaGetSymbolAddress((void**)&xl, g_xl);
    cudaGetSymbolAddress((void**)&aoh, g_aoh);     cudaGetSymbolAddress((void**)&aol, g_aol);
    cudaGetSymbolAddress((void**)&f1h, g_f1h);     cudaGetSymbolAddress((void**)&f1l, g_f1l);
    cudaGetSymbolAddress((void**)&x, g_x);
    cudaGetSymbolAddress((void**)&qkvf, g_qkv);
    cudaGetSymbolAddress((void**)&obuf, g_obuf);
    cudaGetSymbolAddress((void**)&obuf2, g_obuf2);
    cudaGetSymbolAddress((void**)&f2, g_f2);
    cudaGetSymbolAddress((void**)&f2b, g_f2b);

    constexpr int SMEM2ST = 40960, SMEM3ST = 61440;
    cudaFuncSetAttribute(gemm_mma<false, true,  true,  1, 3>, cudaFuncAttributeMaxDynamicSharedMemorySize, SMEM3ST);
    cudaFuncSetAttribute(gemm_mma<false, true,  false, 1, 3>, cudaFuncAttributeMaxDynamicSharedMemorySize, SMEM3ST);
    cudaFuncSetAttribute(gemm_mma<false, true,  false, 2, 3>, cudaFuncAttributeMaxDynamicSharedMemorySize, SMEM3ST);
    cudaFuncSetAttribute(gemm_mma<true,  false, true,  1, 2>, cudaFuncAttributeMaxDynamicSharedMemorySize, SMEM2ST);

    // fused embed (4 tok/block) + weight hi/lo convert — one launch
    embed_convert_kernel<<<EMB_BLKS + CVT_BLKS, 512>>>(
        word, ngram, fc1_w, fc1_b, h0h, h0l,
        fc2_w, qkv_w, out_w, ff1_w, ff2_w,
        wfc2h, wfc2l, wqkvh, wqkvl, wouth, woutl, wff1h, wff1l, wff2h, wff2l);

    // fc2: x = h0 @ fc2_w^T + b  [2048, 256]  (fp32 + hi/lo out) — grid 4x32, 3-stage
    gemm_mma<false, true, true, 1, 3><<<dim3(Dz / 64, Tz / 64), 256, SMEM3ST>>>(
        h0h, h0l, wfc2h, wfc2l, fc2_b, x, xh, xl, nullptr, Dz, FFDz);

    for (int i = 0; i < NLz; i++) {
        const __nv_bfloat16* qwh = wqkvh + (size_t)i * 3 * Dz * Dz;
        const __nv_bfloat16* qwl = wqkvl + (size_t)i * 3 * Dz * Dz;
        const __nv_bfloat16* owh = wouth + (size_t)i * Dz * Dz;
        const __nv_bfloat16* owl = woutl + (size_t)i * Dz * Dz;
        const __nv_bfloat16* f1wh = wff1h + (size_t)i * DFFz * Dz;
        const __nv_bfloat16* f1wl = wff1l + (size_t)i * DFFz * Dz;
        const __nv_bfloat16* f2wh = wff2h + (size_t)i * Dz * DFFz;
        const __nv_bfloat16* f2wl = wff2l + (size_t)i * Dz * DFFz;

        // qkv projection [2048, 768] — grid 12x32 (384 CTAs), 3-stage
        gemm_mma<false, true, false, 1, 3><<<dim3(3 * Dz / 64, Tz / 64), 256, SMEM3ST>>>(
            xh, xl, qwh, qwl, qkv_b + (size_t)i * 3 * Dz, qkvf, nullptr, nullptr, nullptr, 3 * Dz, Dz);
        // attention — grid 256, 2 query rows per thread
        attn_kernel<<<Bz * Hz, 256>>>(qkvf, aoh, aol);
        // out projection [2048, 256], K=256 split-K=2 — grid 4x32x2 (256 CTAs), 3-stage
        gemm_mma<false, true, false, 2, 3><<<dim3(Dz / 64, Tz / 64, 2), 256, SMEM3ST>>>(
            aoh, aol, owh, owl, out_b + (size_t)i * Dz, obuf, nullptr, nullptr, obuf2, Dz, Dz);
        // x = LN(x + obuf + obuf2), fp32 + hi/lo
        add_ln_kernel<<<Tz, 256>>>(x, obuf, obuf2, ln1_g + i * Dz, ln1_b + i * Dz, x, xh, xl);
        // ff1 + relu [2048, 1024] hi/lo only — grid 16x32 (512 CTAs), 2-stage
        gemm_mma<true, false, true, 1, 2><<<dim3(DFFz / 64, Tz / 64), 256, SMEM2ST>>>(
            xh, xl, f1wh, f1wl, ff1_b + (size_t)i * DFFz, nullptr, f1h, f1l, nullptr, DFFz, Dz);
        // ff2 [2048, 256], K=1024 split-K=2 — grid 4x32x2 (256 CTAs), 3-stage
        gemm_mma<false, true, false, 2, 3><<<dim3(Dz / 64, Tz / 64, 2), 256, SMEM3ST>>>(
            f1h, f1l, f2wh, f2wl, ff2_b + (size_t)i * Dz, f2, nullptr, nullptr, f2b, Dz, DFFz);
        // x = LN(x + f2 + f2b); final layer -> d_out (fp32 only)
        bool last = (i == NLz - 1);
        add_ln_kernel<<<Tz, 256>>>(x, f2, f2b, ln2_g + i * Dz, ln2_b + i * Dz,
                                   last ? outp : x,
                                   last ? nullptr : xh, last ? nullptr : xl);
    }
}